// round 1
// baseline (speedup 1.0000x reference)
#include <cuda_runtime.h>

// ---------------------------------------------------------------------------
// AtomUpdateBlock:
//   x2[a,:]  = sum_{e: id_j[e]=a} m[e,:] * (rbf[e,:] @ W_rbf.T)      (scatter)
//   y0 = ssilu(scale * x2 @ W1.T)
//   for i in 0..1:  h = ssilu(ssilu(y @ Wres[i,0].T) @ Wres[i,1].T)
//                   y = (y + h) * 2^-0.5
// ---------------------------------------------------------------------------

#define CAP_ATOMS 131072
__device__ float g_x2[CAP_ATOMS * 128];
__device__ float g_a [CAP_ATOMS * 128];
__device__ float g_b [CAP_ATOMS * 128];

__device__ __forceinline__ float ssilu(float x) {
    // silu(x) / 0.6
    return x * (1.0f / (1.0f + __expf(-x))) * 1.6666666666666667f;
}

// ---------------------------------------------------------------------------
// zero the scatter accumulator
// ---------------------------------------------------------------------------
__global__ void __launch_bounds__(256) zero_kernel(float* __restrict__ p, int n4) {
    int i = blockIdx.x * blockDim.x + threadIdx.x;
    int stride = gridDim.x * blockDim.x;
    float4 z = make_float4(0.f, 0.f, 0.f, 0.f);
    for (; i < n4; i += stride) ((float4*)p)[i] = z;
}

// ---------------------------------------------------------------------------
// Edge kernel: warp per edge. Lane L owns output channels 4L..4L+3.
// W_rbf rows for those channels live packed (f32x2) in registers.
// per edge: 32 FFMA2 / lane-equiv + 1 red.global.add.v4.f32 per lane.
// ---------------------------------------------------------------------------
__global__ void __launch_bounds__(256) edge_kernel(
    const float* __restrict__ m,      // [E,128]
    const float* __restrict__ rbf,    // [E,16]
    const int*   __restrict__ idj,    // [E]
    const float* __restrict__ Wr,     // [128,16] (torch [out,in])
    float*       __restrict__ out,    // [nAtoms,128] accumulator
    int E)
{
    const int lane  = threadIdx.x & 31;
    const int warp  = (blockIdx.x * blockDim.x + threadIdx.x) >> 5;
    const int nwarp = (gridDim.x * blockDim.x) >> 5;
    const int c0 = lane * 4;

    // Preload packed weights: wp0[k] = {W[c0][k], W[c0+1][k]}, wp1[k] = {W[c0+2][k], W[c0+3][k]}
    unsigned long long wp0[16], wp1[16];
#pragma unroll
    for (int k = 0; k < 16; ++k) {
        float a = Wr[(c0 + 0) * 16 + k];
        float b = Wr[(c0 + 1) * 16 + k];
        float c = Wr[(c0 + 2) * 16 + k];
        float d = Wr[(c0 + 3) * 16 + k];
        asm("mov.b64 %0, {%1, %2};" : "=l"(wp0[k]) : "f"(a), "f"(b));
        asm("mov.b64 %0, {%1, %2};" : "=l"(wp1[k]) : "f"(c), "f"(d));
    }

    for (int e = warp; e < E; e += nwarp) {
        const int atom = __ldg(idj + e);
        const float4* rb4 = (const float4*)(rbf + (size_t)e * 16);
        float4 r0 = __ldg(rb4 + 0);
        float4 r1 = __ldg(rb4 + 1);
        float4 r2 = __ldg(rb4 + 2);
        float4 r3 = __ldg(rb4 + 3);
        float rk[16];
        rk[0]=r0.x; rk[1]=r0.y; rk[2]=r0.z; rk[3]=r0.w;
        rk[4]=r1.x; rk[5]=r1.y; rk[6]=r1.z; rk[7]=r1.w;
        rk[8]=r2.x; rk[9]=r2.y; rk[10]=r2.z; rk[11]=r2.w;
        rk[12]=r3.x; rk[13]=r3.y; rk[14]=r3.z; rk[15]=r3.w;

        unsigned long long acc0 = 0ull, acc1 = 0ull;   // {0.f,0.f}
#pragma unroll
        for (int k = 0; k < 16; ++k) {
            unsigned long long rp;
            asm("mov.b64 %0, {%1, %1};" : "=l"(rp) : "f"(rk[k]));
            asm("fma.rn.f32x2 %0, %1, %2, %0;" : "+l"(acc0) : "l"(rp), "l"(wp0[k]));
            asm("fma.rn.f32x2 %0, %1, %2, %0;" : "+l"(acc1) : "l"(rp), "l"(wp1[k]));
        }

        float4 mv = __ldg((const float4*)(m + (size_t)e * 128) + lane);
        float v0, v1, v2, v3;
        asm("mov.b64 {%0, %1}, %2;" : "=f"(v0), "=f"(v1) : "l"(acc0));
        asm("mov.b64 {%0, %1}, %2;" : "=f"(v2), "=f"(v3) : "l"(acc1));
        v0 *= mv.x; v1 *= mv.y; v2 *= mv.z; v3 *= mv.w;

        float* dst = out + (size_t)atom * 128 + c0;
        asm volatile("red.global.add.v4.f32 [%0], {%1, %2, %3, %4};"
                     :: "l"(dst), "f"(v0), "f"(v1), "f"(v2), "f"(v3) : "memory");
    }
}

// ---------------------------------------------------------------------------
// MLP GEMM: out[r,c] = post( sum_k X[r,k] * W[c,k] )
//   post:  y = ssilu(prescale * dot);  if res: y = (res[r,c] + y) * 2^-0.5
// BM=64 rows per block, full N=K=128.  256 threads, thread tile 8 rows x 4 cols.
// Smem: As[k][r] (pad 68), Ws[k][c] (pad 132) -> 100 KB dynamic, 2 CTAs/SM.
// Transposed-thread global loads keep both LDG (coalesced) and STS.128
// (consecutive-k lanes -> distinct bank groups) conflict-free.
// ---------------------------------------------------------------------------
#define MLP_SMEM_BYTES ((128 * 68 + 128 * 132) * 4)

__global__ void __launch_bounds__(256, 2) mlp_kernel(
    const float* __restrict__ X,          // [nRows,128]
    const float* __restrict__ W,          // [128,128] row-major [out,in]
    const float* __restrict__ res,        // [nRows,128] or null
    const float* __restrict__ scale_ptr,  // scalar or null
    float*       __restrict__ out,        // [nRows,128]
    int nRows)
{
    extern __shared__ float smem[];
    float* As = smem;                 // [128][68]
    float* Ws = smem + 128 * 68;      // [128][132]

    const int tid  = threadIdx.x;
    const int row0 = blockIdx.x * 64;
    const float pre = scale_ptr ? __ldg(scale_ptr) : 1.0f;

    // --- load W transposed: thread i handles (c4 = i>>7, k = i&127), 4 scalar
    //     coalesced LDG over k-lanes, one STS.128 (conflict-free).
    for (int i = tid; i < 32 * 128; i += 256) {
        int c4 = i >> 7, k = i & 127;
        float w0 = __ldg(&W[(4 * c4 + 0) * 128 + k]);
        float w1 = __ldg(&W[(4 * c4 + 1) * 128 + k]);
        float w2 = __ldg(&W[(4 * c4 + 2) * 128 + k]);
        float w3 = __ldg(&W[(4 * c4 + 3) * 128 + k]);
        *(float4*)&Ws[k * 132 + 4 * c4] = make_float4(w0, w1, w2, w3);
    }
    // --- load A transposed the same way
    for (int i = tid; i < 16 * 128; i += 256) {
        int r4 = i >> 7, k = i & 127;
        int r = 4 * r4;
        float a0 = (row0 + r + 0 < nRows) ? X[(size_t)(row0 + r + 0) * 128 + k] : 0.f;
        float a1 = (row0 + r + 1 < nRows) ? X[(size_t)(row0 + r + 1) * 128 + k] : 0.f;
        float a2 = (row0 + r + 2 < nRows) ? X[(size_t)(row0 + r + 2) * 128 + k] : 0.f;
        float a3 = (row0 + r + 3 < nRows) ? X[(size_t)(row0 + r + 3) * 128 + k] : 0.f;
        *(float4*)&As[k * 68 + r] = make_float4(a0, a1, a2, a3);
    }
    __syncthreads();

    const int c0 = (tid & 31) * 4;        // 4 consecutive cols
    const int r0 = (tid >> 5) * 8;        // 8 consecutive rows (warp-uniform)

    unsigned long long acc[8][2];
#pragma unroll
    for (int r = 0; r < 8; ++r) { acc[r][0] = 0ull; acc[r][1] = 0ull; }

#pragma unroll 8
    for (int k = 0; k < 128; ++k) {
        // W: contiguous 512B LDS.128 across warp; reinterpret as two f32x2 packs
        ulonglong2 wv = *(const ulonglong2*)&Ws[k * 132 + c0];
        // A: warp-uniform broadcast loads
        float4 a0 = *(const float4*)&As[k * 68 + r0];
        float4 a1 = *(const float4*)&As[k * 68 + r0 + 4];
        float ar[8];
        ar[0]=a0.x; ar[1]=a0.y; ar[2]=a0.z; ar[3]=a0.w;
        ar[4]=a1.x; ar[5]=a1.y; ar[6]=a1.z; ar[7]=a1.w;
#pragma unroll
        for (int r = 0; r < 8; ++r) {
            unsigned long long ap;
            asm("mov.b64 %0, {%1, %1};" : "=l"(ap) : "f"(ar[r]));
            asm("fma.rn.f32x2 %0, %1, %2, %0;" : "+l"(acc[r][0]) : "l"(ap), "l"(wv.x));
            asm("fma.rn.f32x2 %0, %1, %2, %0;" : "+l"(acc[r][1]) : "l"(ap), "l"(wv.y));
        }
    }

    const float inv_sqrt2 = 0.70710678118654752440f;
#pragma unroll
    for (int r = 0; r < 8; ++r) {
        int row = row0 + r0 + r;
        if (row >= nRows) continue;
        float v0, v1, v2, v3;
        asm("mov.b64 {%0, %1}, %2;" : "=f"(v0), "=f"(v1) : "l"(acc[r][0]));
        asm("mov.b64 {%0, %1}, %2;" : "=f"(v2), "=f"(v3) : "l"(acc[r][1]));
        float4 y;
        y.x = ssilu(pre * v0);
        y.y = ssilu(pre * v1);
        y.z = ssilu(pre * v2);
        y.w = ssilu(pre * v3);
        if (res) {
            float4 rv = *(const float4*)&res[(size_t)row * 128 + c0];
            y.x = (rv.x + y.x) * inv_sqrt2;
            y.y = (rv.y + y.y) * inv_sqrt2;
            y.z = (rv.z + y.z) * inv_sqrt2;
            y.w = (rv.w + y.w) * inv_sqrt2;
        }
        *(float4*)&out[(size_t)row * 128 + c0] = y;
    }
}

// ---------------------------------------------------------------------------
extern "C" void kernel_launch(void* const* d_in, const int* in_sizes, int n_in,
                              void* d_out, int out_size)
{
    // metadata order: nAtoms, m, rbf, id_j, W_rbf, scale, W1, W_res
    const float* m     = (const float*)d_in[1];
    const float* rbf   = (const float*)d_in[2];
    const int*   idj   = (const int*)  d_in[3];
    const float* Wrbf  = (const float*)d_in[4];
    const float* scale = (const float*)d_in[5];
    const float* W1    = (const float*)d_in[6];
    const float* Wres  = (const float*)d_in[7];

    int E      = in_sizes[1] / 128;
    int nAtoms = out_size / 128;
    if (nAtoms > CAP_ATOMS) nAtoms = CAP_ATOMS;

    float *px2 = nullptr, *pa = nullptr, *pb = nullptr;
    cudaGetSymbolAddress((void**)&px2, g_x2);
    cudaGetSymbolAddress((void**)&pa,  g_a);
    cudaGetSymbolAddress((void**)&pb,  g_b);

    cudaFuncSetAttribute(mlp_kernel, cudaFuncAttributeMaxDynamicSharedMemorySize,
                         MLP_SMEM_BYTES);

    int n4 = nAtoms * 128 / 4;
    zero_kernel<<<2048, 256>>>(px2, n4);
    edge_kernel<<<4096, 256>>>(m, rbf, idj, Wrbf, px2, E);

    int grid = (nAtoms + 63) / 64;
    float* dout = (float*)d_out;
    // y0 = ssilu(scale * x2 @ W1.T)
    mlp_kernel<<<grid, 256, MLP_SMEM_BYTES>>>(px2, W1, nullptr, scale, pa, nAtoms);
    // h = ssilu(y0 @ Wres[0,0].T)
    mlp_kernel<<<grid, 256, MLP_SMEM_BYTES>>>(pa, Wres + 0 * 16384, nullptr, nullptr, pb, nAtoms);
    // y1 = (y0 + ssilu(h @ Wres[0,1].T)) * inv_sqrt2
    mlp_kernel<<<grid, 256, MLP_SMEM_BYTES>>>(pb, Wres + 1 * 16384, pa, nullptr, px2, nAtoms);
    // h = ssilu(y1 @ Wres[1,0].T)
    mlp_kernel<<<grid, 256, MLP_SMEM_BYTES>>>(px2, Wres + 2 * 16384, nullptr, nullptr, pb, nAtoms);
    // out = (y1 + ssilu(h @ Wres[1,1].T)) * inv_sqrt2
    mlp_kernel<<<grid, 256, MLP_SMEM_BYTES>>>(pb, Wres + 3 * 16384, px2, nullptr, dout, nAtoms);
}